// round 13
// baseline (speedup 1.0000x reference)
#include <cuda_runtime.h>
#include <cuda_fp16.h>
#include <cstdint>

// Problem dims (fixed by reference setup_inputs)
#define MM   8192      // B*S
#define NN   4096      // D_OUT
#define KK   4096      // D_IN
#define RR   16
#define LORA_SCALING 2.0f

// ---------------------------------------------------------------------------
// Device scratch (static __device__ arrays — no runtime allocation)
// ---------------------------------------------------------------------------
__device__ __half g_xh[(size_t)MM * KK];   // 64 MB: x rounded to fp16
__device__ __half g_wh[(size_t)NN * KK];   // 32 MB: fused dequant+LoRA weight, fp16

// ---------------------------------------------------------------------------
// Helpers (base PTX only — sm_103 target has no 'a'-feature instructions)
// ---------------------------------------------------------------------------
__device__ __forceinline__ uint32_t smem_u32(const void* p) {
    uint32_t a;
    asm("{ .reg .u64 t; cvta.to.shared.u64 t, %1; cvt.u32.u64 %0, t; }"
        : "=r"(a) : "l"(p));
    return a;
}

#define CP_ASYNC16(dst_u32, src_ptr) \
    asm volatile("cp.async.cg.shared.global [%0], [%1], 16;\n" :: "r"(dst_u32), "l"(src_ptr))
#define CP_COMMIT()   asm volatile("cp.async.commit_group;\n" ::)
#define CP_WAIT(n)    asm volatile("cp.async.wait_group %0;\n" :: "n"(n))

#define LDMATRIX_X4(r0, r1, r2, r3, addr)                                     \
    asm volatile("ldmatrix.sync.aligned.m8n8.x4.shared.b16 {%0,%1,%2,%3}, [%4];" \
        : "=r"(r0), "=r"(r1), "=r"(r2), "=r"(r3) : "r"(addr))

#define MMA16816(d, a, b)                                                      \
    asm volatile("mma.sync.aligned.m16n8k16.row.col.f32.f16.f16.f32 "          \
        "{%0,%1,%2,%3}, {%4,%5,%6,%7}, {%8,%9}, {%0,%1,%2,%3};\n"              \
        : "+f"((d)[0]), "+f"((d)[1]), "+f"((d)[2]), "+f"((d)[3])               \
        : "r"((a)[0]), "r"((a)[1]), "r"((a)[2]), "r"((a)[3]),                  \
          "r"((b)[0]), "r"((b)[1]))

// ---------------------------------------------------------------------------
// Kernel 1: x (fp32) -> fp16  (8 elems / thread, fully vectorized)
// ---------------------------------------------------------------------------
__global__ void conv_x_kernel(const float4* __restrict__ x) {
    size_t i = (size_t)blockIdx.x * blockDim.x + threadIdx.x;
    size_t n8 = (size_t)MM * KK / 8;
    if (i < n8) {
        float4 a = x[2 * i], b = x[2 * i + 1];
        __half2 h0 = __floats2half2_rn(a.x, a.y);
        __half2 h1 = __floats2half2_rn(a.z, a.w);
        __half2 h2 = __floats2half2_rn(b.x, b.y);
        __half2 h3 = __floats2half2_rn(b.z, b.w);
        uint4 o;
        o.x = *reinterpret_cast<unsigned*>(&h0);
        o.y = *reinterpret_cast<unsigned*>(&h1);
        o.z = *reinterpret_cast<unsigned*>(&h2);
        o.w = *reinterpret_cast<unsigned*>(&h3);
        ((uint4*)g_xh)[i] = o;
    }
}

// ---------------------------------------------------------------------------
// Kernel 2: W_eff = (wq - zero)*scale + 2 * B @ A  -> fp16
// ---------------------------------------------------------------------------
__global__ void build_weff_kernel(const int* __restrict__ wq,
                                  const float* __restrict__ scale,
                                  const float* __restrict__ zero,
                                  const float* __restrict__ lA,
                                  const float* __restrict__ lB) {
    constexpr int BO = 64, BI = 256;
    __shared__ float sA[RR][BI];
    __shared__ float sB[BO][RR];
    __shared__ float sS[BO], sZ[BO];

    const int i0 = blockIdx.x * BI;
    const int o0 = blockIdx.y * BO;
    const int tid = threadIdx.x;

    for (int idx = tid; idx < RR * BI; idx += 256) {
        int r = idx / BI, i = idx % BI;
        sA[r][i] = lA[(size_t)r * KK + i0 + i];
    }
    for (int idx = tid; idx < BO * RR; idx += 256) {
        int o = idx / RR, r = idx % RR;
        sB[o][r] = lB[(size_t)(o0 + o) * RR + r];
    }
    if (tid < BO) { sS[tid] = scale[o0 + tid]; sZ[tid] = zero[o0 + tid]; }
    __syncthreads();

    for (int idx = tid; idx < BO * BI / 2; idx += 256) {
        int o = idx / (BI / 2), i2 = (idx % (BI / 2)) * 2;
        const int* wrow = wq + (size_t)(o0 + o) * KK + i0;
        float z = sZ[o], s = sS[o];
        float w0 = ((float)wrow[i2] - z) * s;
        float w1 = ((float)wrow[i2 + 1] - z) * s;
        float a0 = 0.f, a1 = 0.f;
        #pragma unroll
        for (int r = 0; r < RR; r++) {
            a0 += sB[o][r] * sA[r][i2];
            a1 += sB[o][r] * sA[r][i2 + 1];
        }
        __half2 h = __floats2half2_rn(w0 + LORA_SCALING * a0, w1 + LORA_SCALING * a1);
        *reinterpret_cast<__half2*>(g_wh + (size_t)(o0 + o) * KK + i0 + i2) = h;
    }
}

// ---------------------------------------------------------------------------
// Kernel 3: fp16 mma.sync GEMM.  C[m,n] = sum_k xh[m,k]*wh[n,k] + bias[n]
// CTA tile 128x256x64, 4-stage cp.async, SW128 xor swizzle, ldmatrix frags.
// 8 warps: 2(M) x 4(N); warp tile 64x64 (4 m16-tiles x 8 n8-tiles).
// ---------------------------------------------------------------------------
constexpr int BM = 128, BN = 256, BK = 64;     // halves; BK*2 = 128B rows (SW128)
constexpr int NSTAGES = 4;
constexpr int A_ST = BM * 128;                 // 16 KB per stage
constexpr int B_ST = BN * 128;                 // 32 KB per stage
constexpr int STG  = A_ST + B_ST;              // 48 KB per stage
constexpr int GEMM_SMEM = NSTAGES * STG + 128; // 192 KB + align slack
constexpr int KT = KK / BK;                    // 64

__global__ void __launch_bounds__(256, 1)
gemm_fp16_kernel(const float* __restrict__ bias, float* __restrict__ C) {
    extern __shared__ char dsm[];
    const uint32_t tile = (smem_u32(dsm) + 127u) & ~127u;   // 128B-align

    const int tid  = threadIdx.x;
    const int warp = tid >> 5;
    const int lane = tid & 31;
    const int m0 = blockIdx.y * BM;
    const int n0 = blockIdx.x * BN;

    // ---- cp.async mapping: c16 = tid&7 fixed; rows step 32 per chunk-slot ----
    // A: 128 rows x 8 chunks = 1024 chunks -> slots j=0..3 (row = tid>>3 + j*32)
    // B: 256 rows x 8 chunks = 2048 chunks -> slots j=0..7 (row = tid>>3 + j*32)
    const int c16 = tid & 7;
    const int lrow = tid >> 3;                 // 0..31
    const __half* gAp = g_xh + (size_t)(m0 + lrow) * KK + c16 * 8;
    const __half* gBp = g_wh + (size_t)(n0 + lrow) * KK + c16 * 8;
    // row steps of 32 keep row&7 constant -> swizzle offset invariant per slot
    const uint32_t dA0 = (uint32_t)(lrow * 128 + ((c16 ^ (lrow & 7)) << 4));
    const uint32_t dB0 = dA0 + A_ST;           // same row/c16 pattern, B region

    #define ISSUE_STAGE(kt_, s_) do {                                          \
        uint32_t base_ = tile + (s_) * STG;                                    \
        const __half* pa_ = gAp + (kt_) * BK;                                  \
        const __half* pb_ = gBp + (kt_) * BK;                                  \
        _Pragma("unroll")                                                      \
        for (int j = 0; j < 4; j++)                                            \
            CP_ASYNC16(base_ + dA0 + j * 4096, pa_ + (size_t)j * 32 * KK);     \
        _Pragma("unroll")                                                      \
        for (int j = 0; j < 8; j++)                                            \
            CP_ASYNC16(base_ + dB0 + j * 4096, pb_ + (size_t)j * 32 * KK);     \
        CP_COMMIT();                                                           \
    } while (0)

    // ---- warp/fragment geometry: 2 M-warps x 4 N-warps, warp tile 64x64 ----
    const int wm = (warp >> 2) * 64;       // 0 or 64
    const int wn = (warp & 3) * 64;        // 0,64,128,192
    const int gid = lane >> 2;             // 0..7
    const int tig = lane & 3;              // 0..3
    const int l7  = lane & 7;

    // A (x4, non-trans): lanes 0-15 rows (lane&15), chunk delta lane>>4
    uint32_t a_row[4];
    #pragma unroll
    for (int mi = 0; mi < 4; mi++)
        a_row[mi] = (uint32_t)((wm + mi * 16 + (lane & 15)) * 128);
    const uint32_t a_cx = (uint32_t)(lane >> 4);
    // B (x4, non-trans): rows l7 + ((lane>>4)<<3), chunk delta (lane>>3)&1
    uint32_t b_row[4];
    #pragma unroll
    for (int ng = 0; ng < 4; ng++)
        b_row[ng] = (uint32_t)((wn + ng * 16 + l7 + ((lane >> 4) << 3)) * 128);
    const uint32_t b_cx = (uint32_t)((lane >> 3) & 1);

    float acc[4][8][4];
    #pragma unroll
    for (int a = 0; a < 4; a++)
        #pragma unroll
        for (int b = 0; b < 8; b++)
            #pragma unroll
            for (int c = 0; c < 4; c++) acc[a][b][c] = 0.f;

    ISSUE_STAGE(0, 0);
    ISSUE_STAGE(1, 1);
    ISSUE_STAGE(2, 2);

    int s = 0;
    for (int kt = 0; kt < KT; kt++) {
        CP_WAIT(2);                       // oldest pending group (stage kt) done
        __syncthreads();                  // all warps done reading stage (kt-1)%4
        if (kt + 3 < KT) {
            int sn = s + 3; if (sn >= NSTAGES) sn -= NSTAGES;
            ISSUE_STAGE(kt + 3, sn);
        }

        const uint32_t sA = tile + s * STG;
        const uint32_t sB = sA + A_ST;

        #pragma unroll
        for (int ks = 0; ks < 4; ks++) {          // 4 x k16 per BK=64
            const uint32_t kc = (uint32_t)(ks * 2);
            uint32_t af[4][4], bf[8][2];
            #pragma unroll
            for (int mi = 0; mi < 4; mi++) {
                uint32_t addr = sA + a_row[mi] + (((kc + a_cx) ^ l7) << 4);
                LDMATRIX_X4(af[mi][0], af[mi][1], af[mi][2], af[mi][3], addr);
            }
            #pragma unroll
            for (int ng = 0; ng < 4; ng++) {
                uint32_t addr = sB + b_row[ng] + (((kc + b_cx) ^ l7) << 4);
                LDMATRIX_X4(bf[2 * ng][0], bf[2 * ng][1],
                            bf[2 * ng + 1][0], bf[2 * ng + 1][1], addr);
            }
            #pragma unroll
            for (int mi = 0; mi < 4; mi++)
                #pragma unroll
                for (int ni = 0; ni < 8; ni++)
                    MMA16816(acc[mi][ni], af[mi], bf[ni]);
        }
        if (++s == NSTAGES) s = 0;
    }

    // ---- epilogue: + bias, float2 stores ----
    #pragma unroll
    for (int mi = 0; mi < 4; mi++) {
        const int row0 = m0 + wm + mi * 16 + gid;
        #pragma unroll
        for (int ni = 0; ni < 8; ni++) {
            const int col = n0 + wn + ni * 8 + tig * 2;
            const float b0 = __ldg(bias + col);
            const float b1 = __ldg(bias + col + 1);
            float2 v0 = make_float2(acc[mi][ni][0] + b0, acc[mi][ni][1] + b1);
            float2 v1 = make_float2(acc[mi][ni][2] + b0, acc[mi][ni][3] + b1);
            *(float2*)(C + (size_t)row0 * NN + col)       = v0;
            *(float2*)(C + (size_t)(row0 + 8) * NN + col) = v1;
        }
    }
    #undef ISSUE_STAGE
}

// ---------------------------------------------------------------------------
// Launch
// ---------------------------------------------------------------------------
extern "C" void kernel_launch(void* const* d_in, const int* in_sizes, int n_in,
                              void* d_out, int out_size) {
    const float* x     = (const float*)d_in[0];
    const int*   wq    = (const int*)  d_in[1];
    const float* scale = (const float*)d_in[2];
    const float* zero  = (const float*)d_in[3];
    const float* lA    = (const float*)d_in[4];
    const float* lB    = (const float*)d_in[5];
    const float* bias  = (const float*)d_in[6];
    float* out = (float*)d_out;

    cudaFuncSetAttribute(gemm_fp16_kernel,
                         cudaFuncAttributeMaxDynamicSharedMemorySize, GEMM_SMEM);

    // 1) x -> fp16
    {
        size_t n8 = (size_t)MM * KK / 8;
        conv_x_kernel<<<(int)((n8 + 255) / 256), 256>>>((const float4*)x);
    }
    // 2) fused dequant + LoRA -> fp16 effective weight
    {
        dim3 grid(KK / 256, NN / 64);
        build_weff_kernel<<<grid, 256>>>(wq, scale, zero, lA, lB);
    }
    // 3) fp16 tensor-core GEMM + bias
    {
        dim3 grid(NN / BN, MM / BM);   // (16, 64)
        gemm_fp16_kernel<<<grid, 256, GEMM_SMEM>>>(bias, out);
    }
}

// round 14
// speedup vs baseline: 1.0637x; 1.0637x over previous
#include <cuda_runtime.h>
#include <cuda_fp16.h>
#include <cstdint>

// Problem dims (fixed by reference setup_inputs)
#define MM   8192      // B*S
#define NN   4096      // D_OUT
#define KK   4096      // D_IN
#define RR   16
#define LORA_SCALING 2.0f

// ---------------------------------------------------------------------------
// Device scratch (static __device__ arrays — no runtime allocation)
// ---------------------------------------------------------------------------
__device__ __half g_xh[(size_t)MM * KK];   // 64 MB: x rounded to fp16
__device__ __half g_wh[(size_t)NN * KK];   // 32 MB: fused dequant+LoRA weight, fp16

// ---------------------------------------------------------------------------
// Helpers (base PTX only — sm_103 target has no 'a'-feature instructions)
// ---------------------------------------------------------------------------
__device__ __forceinline__ uint32_t smem_u32(const void* p) {
    uint32_t a;
    asm("{ .reg .u64 t; cvta.to.shared.u64 t, %1; cvt.u32.u64 %0, t; }"
        : "=r"(a) : "l"(p));
    return a;
}

#define CP_ASYNC16(dst_u32, src_ptr) \
    asm volatile("cp.async.cg.shared.global [%0], [%1], 16;\n" :: "r"(dst_u32), "l"(src_ptr))
#define CP_COMMIT()   asm volatile("cp.async.commit_group;\n" ::)
#define CP_WAIT(n)    asm volatile("cp.async.wait_group %0;\n" :: "n"(n))

#define LDMATRIX_X4(r0, r1, r2, r3, addr)                                     \
    asm volatile("ldmatrix.sync.aligned.m8n8.x4.shared.b16 {%0,%1,%2,%3}, [%4];" \
        : "=r"(r0), "=r"(r1), "=r"(r2), "=r"(r3) : "r"(addr))

#define MMA16816(d, a, b)                                                      \
    asm volatile("mma.sync.aligned.m16n8k16.row.col.f32.f16.f16.f32 "          \
        "{%0,%1,%2,%3}, {%4,%5,%6,%7}, {%8,%9}, {%0,%1,%2,%3};\n"              \
        : "+f"((d)[0]), "+f"((d)[1]), "+f"((d)[2]), "+f"((d)[3])               \
        : "r"((a)[0]), "r"((a)[1]), "r"((a)[2]), "r"((a)[3]),                  \
          "r"((b)[0]), "r"((b)[1]))

// ---------------------------------------------------------------------------
// Kernel 1: x (fp32) -> fp16  (8 elems / thread, fully vectorized)
// ---------------------------------------------------------------------------
__global__ void conv_x_kernel(const float4* __restrict__ x) {
    size_t i = (size_t)blockIdx.x * blockDim.x + threadIdx.x;
    size_t n8 = (size_t)MM * KK / 8;
    if (i < n8) {
        float4 a = x[2 * i], b = x[2 * i + 1];
        __half2 h0 = __floats2half2_rn(a.x, a.y);
        __half2 h1 = __floats2half2_rn(a.z, a.w);
        __half2 h2 = __floats2half2_rn(b.x, b.y);
        __half2 h3 = __floats2half2_rn(b.z, b.w);
        uint4 o;
        o.x = *reinterpret_cast<unsigned*>(&h0);
        o.y = *reinterpret_cast<unsigned*>(&h1);
        o.z = *reinterpret_cast<unsigned*>(&h2);
        o.w = *reinterpret_cast<unsigned*>(&h3);
        ((uint4*)g_xh)[i] = o;
    }
}

// ---------------------------------------------------------------------------
// Kernel 2: W_eff = (wq - zero)*scale + 2 * B @ A  -> fp16
// ---------------------------------------------------------------------------
__global__ void build_weff_kernel(const int* __restrict__ wq,
                                  const float* __restrict__ scale,
                                  const float* __restrict__ zero,
                                  const float* __restrict__ lA,
                                  const float* __restrict__ lB) {
    constexpr int BO = 64, BI = 256;
    __shared__ float sA[RR][BI];
    __shared__ float sB[BO][RR];
    __shared__ float sS[BO], sZ[BO];

    const int i0 = blockIdx.x * BI;
    const int o0 = blockIdx.y * BO;
    const int tid = threadIdx.x;

    for (int idx = tid; idx < RR * BI; idx += 256) {
        int r = idx / BI, i = idx % BI;
        sA[r][i] = lA[(size_t)r * KK + i0 + i];
    }
    for (int idx = tid; idx < BO * RR; idx += 256) {
        int o = idx / RR, r = idx % RR;
        sB[o][r] = lB[(size_t)(o0 + o) * RR + r];
    }
    if (tid < BO) { sS[tid] = scale[o0 + tid]; sZ[tid] = zero[o0 + tid]; }
    __syncthreads();

    for (int idx = tid; idx < BO * BI / 2; idx += 256) {
        int o = idx / (BI / 2), i2 = (idx % (BI / 2)) * 2;
        const int* wrow = wq + (size_t)(o0 + o) * KK + i0;
        float z = sZ[o], s = sS[o];
        float w0 = ((float)wrow[i2] - z) * s;
        float w1 = ((float)wrow[i2 + 1] - z) * s;
        float a0 = 0.f, a1 = 0.f;
        #pragma unroll
        for (int r = 0; r < RR; r++) {
            a0 += sB[o][r] * sA[r][i2];
            a1 += sB[o][r] * sA[r][i2 + 1];
        }
        __half2 h = __floats2half2_rn(w0 + LORA_SCALING * a0, w1 + LORA_SCALING * a1);
        *reinterpret_cast<__half2*>(g_wh + (size_t)(o0 + o) * KK + i0 + i2) = h;
    }
}

// ---------------------------------------------------------------------------
// Kernel 3: fp16 mma.sync GEMM.  C[m,n] = sum_k xh[m,k]*wh[n,k] + bias[n]
// CTA tile 128x128x64, 3-stage cp.async, SW128 xor swizzle, occupancy 2.
// 8 warps: 4(M) x 2(N); warp tile 32x64.  Register-level fragment pipelining:
// A frags double-buffered per k16-step, B frag pairs double-buffered per ng.
// ---------------------------------------------------------------------------
constexpr int BM = 128, BN = 128, BK = 64;     // halves; BK*2 = 128B rows (SW128)
constexpr int NSTAGES = 3;
constexpr int A_ST = BM * 128;                 // 16 KB per stage
constexpr int STG = 2 * A_ST;                  // 32 KB per stage (A + B)
constexpr int GEMM_SMEM = NSTAGES * STG + 128; // + align slack
constexpr int KT = KK / BK;                    // 64

__global__ void __launch_bounds__(256, 2)
gemm_fp16_kernel(const float* __restrict__ bias, float* __restrict__ C) {
    extern __shared__ char dsm[];
    const uint32_t tile = (smem_u32(dsm) + 127u) & ~127u;   // 128B-align

    const int tid  = threadIdx.x;
    const int warp = tid >> 5;
    const int lane = tid & 31;
    const int m0 = blockIdx.y * BM;
    const int n0 = blockIdx.x * BN;

    // ---- cp.async mapping (base+stride form): c16 = tid&7, rows step 32 ----
    const int c16 = tid & 7;
    const int lrow = tid >> 3;                 // 0..31
    const __half* gAp = g_xh + (size_t)(m0 + lrow) * KK + c16 * 8;
    const __half* gBp = g_wh + (size_t)(n0 + lrow) * KK + c16 * 8;
    // row steps of 32 keep row&7 constant -> swizzle offset invariant per slot
    const uint32_t dA0 = (uint32_t)(lrow * 128 + ((c16 ^ (lrow & 7)) << 4));
    const uint32_t dB0 = dA0 + A_ST;

    #define ISSUE_STAGE(kt_, s_) do {                                          \
        uint32_t base_ = tile + (s_) * STG;                                    \
        const __half* pa_ = gAp + (kt_) * BK;                                  \
        const __half* pb_ = gBp + (kt_) * BK;                                  \
        _Pragma("unroll")                                                      \
        for (int j = 0; j < 4; j++)                                            \
            CP_ASYNC16(base_ + dA0 + j * 4096, pa_ + (size_t)j * 32 * KK);     \
        _Pragma("unroll")                                                      \
        for (int j = 0; j < 4; j++)                                            \
            CP_ASYNC16(base_ + dB0 + j * 4096, pb_ + (size_t)j * 32 * KK);     \
        CP_COMMIT();                                                           \
    } while (0)

    // ---- warp/fragment geometry (identical to R12-proven mapping) ----
    const int wm = (warp & 3) * 32;        // 4 warps along M
    const int wn = (warp >> 2) * 64;       // 2 warps along N
    const int gid = lane >> 2;             // 0..7
    const int tig = lane & 3;              // 0..3
    const int l7  = lane & 7;

    uint32_t a_row[2];
    #pragma unroll
    for (int mi = 0; mi < 2; mi++)
        a_row[mi] = (uint32_t)((wm + mi * 16 + (lane & 15)) * 128);
    const uint32_t a_cx = (uint32_t)(lane >> 4);        // chunk delta 0/1
    uint32_t b_row[4];
    #pragma unroll
    for (int ng = 0; ng < 4; ng++)
        b_row[ng] = (uint32_t)((wn + ng * 16 + l7 + ((lane >> 4) << 3)) * 128);
    const uint32_t b_cx = (uint32_t)((lane >> 3) & 1);  // chunk delta 0/1

    float acc[2][8][4];
    #pragma unroll
    for (int a = 0; a < 2; a++)
        #pragma unroll
        for (int b = 0; b < 8; b++)
            #pragma unroll
            for (int c = 0; c < 4; c++) acc[a][b][c] = 0.f;

    // fragment double buffers
    uint32_t afb[2][8];   // per-ks A frags (2 ldmatrix.x4)
    uint32_t bfb[2][4];   // per-ng B frag pair (1 ldmatrix.x4)

    #define LOAD_AF(p_, sA_, ks_) do {                                          \
        uint32_t sw_ = ((((uint32_t)((ks_) * 2) + a_cx) ^ l7) << 4);            \
        LDMATRIX_X4(afb[p_][0], afb[p_][1], afb[p_][2], afb[p_][3],             \
                    (sA_) + a_row[0] + sw_);                                    \
        LDMATRIX_X4(afb[p_][4], afb[p_][5], afb[p_][6], afb[p_][7],             \
                    (sA_) + a_row[1] + sw_);                                    \
    } while (0)

    #define LOAD_BF(p_, sB_, ks_, ng_) do {                                     \
        uint32_t sw_ = ((((uint32_t)((ks_) * 2) + b_cx) ^ l7) << 4);            \
        LDMATRIX_X4(bfb[p_][0], bfb[p_][1], bfb[p_][2], bfb[p_][3],             \
                    (sB_) + b_row[ng_] + sw_);                                  \
    } while (0)

    ISSUE_STAGE(0, 0);
    ISSUE_STAGE(1, 1);

    int s = 0;
    for (int kt = 0; kt < KT; kt++) {
        CP_WAIT(1);                       // oldest pending group (stage kt) done
        __syncthreads();                  // all warps done reading stage (kt-1)%3
        if (kt + 2 < KT) {
            int sn = s + 2; if (sn >= NSTAGES) sn -= NSTAGES;
            ISSUE_STAGE(kt + 2, sn);
        }

        const uint32_t sA = tile + s * STG;
        const uint32_t sB = sA + A_ST;

        // prime fragment pipeline for this kt
        LOAD_AF(0, sA, 0);
        LOAD_BF(0, sB, 0, 0);

        #pragma unroll
        for (int g = 0; g < 16; g++) {            // g = ks*4 + ng
            const int ks = g >> 2, ng = g & 3;
            const int pb = g & 1;                  // current B buffer parity
            const int pa = ks & 1;                 // current A buffer parity
            // prefetch next fragments (hidden under the 4 MMAs below)
            if (ng < 3) {
                LOAD_BF(pb ^ 1, sB, ks, ng + 1);
            } else if (ks < 3) {
                LOAD_AF(pa ^ 1, sA, ks + 1);
                LOAD_BF(pb ^ 1, sB, ks + 1, 0);
            }
            MMA16816(acc[0][2 * ng],     afb[pa] + 0, bfb[pb] + 0);
            MMA16816(acc[0][2 * ng + 1], afb[pa] + 0, bfb[pb] + 2);
            MMA16816(acc[1][2 * ng],     afb[pa] + 4, bfb[pb] + 0);
            MMA16816(acc[1][2 * ng + 1], afb[pa] + 4, bfb[pb] + 2);
        }
        if (++s == NSTAGES) s = 0;
    }

    // ---- epilogue: + bias, float2 stores ----
    #pragma unroll
    for (int mi = 0; mi < 2; mi++) {
        const int row0 = m0 + wm + mi * 16 + gid;
        #pragma unroll
        for (int ni = 0; ni < 8; ni++) {
            const int col = n0 + wn + ni * 8 + tig * 2;
            const float b0 = __ldg(bias + col);
            const float b1 = __ldg(bias + col + 1);
            float2 v0 = make_float2(acc[mi][ni][0] + b0, acc[mi][ni][1] + b1);
            float2 v1 = make_float2(acc[mi][ni][2] + b0, acc[mi][ni][3] + b1);
            *(float2*)(C + (size_t)row0 * NN + col)       = v0;
            *(float2*)(C + (size_t)(row0 + 8) * NN + col) = v1;
        }
    }
    #undef ISSUE_STAGE
    #undef LOAD_AF
    #undef LOAD_BF
}

// ---------------------------------------------------------------------------
// Launch
// ---------------------------------------------------------------------------
extern "C" void kernel_launch(void* const* d_in, const int* in_sizes, int n_in,
                              void* d_out, int out_size) {
    const float* x     = (const float*)d_in[0];
    const int*   wq    = (const int*)  d_in[1];
    const float* scale = (const float*)d_in[2];
    const float* zero  = (const float*)d_in[3];
    const float* lA    = (const float*)d_in[4];
    const float* lB    = (const float*)d_in[5];
    const float* bias  = (const float*)d_in[6];
    float* out = (float*)d_out;

    cudaFuncSetAttribute(gemm_fp16_kernel,
                         cudaFuncAttributeMaxDynamicSharedMemorySize, GEMM_SMEM);

    // 1) x -> fp16
    {
        size_t n8 = (size_t)MM * KK / 8;
        conv_x_kernel<<<(int)((n8 + 255) / 256), 256>>>((const float4*)x);
    }
    // 2) fused dequant + LoRA -> fp16 effective weight
    {
        dim3 grid(KK / 256, NN / 64);
        build_weff_kernel<<<grid, 256>>>(wq, scale, zero, lA, lB);
    }
    // 3) fp16 tensor-core GEMM + bias
    {
        dim3 grid(NN / BN, MM / BM);   // (32, 64)
        gemm_fp16_kernel<<<grid, 256, GEMM_SMEM>>>(bias, out);
    }
}